// round 6
// baseline (speedup 1.0000x reference)
#include <cuda_runtime.h>
#include <cstdint>

// Covariance pooling: y[b] = (1/M) X Xᵀ - μ μᵀ, X = x[b] as [C=128, M=4096].
// Symmetry-exploiting tf32 mma.sync version (y is symmetric -> 3 of 4 tiles).
// Kernel 1 (partial): 256 CTAs:
//   blk 0..127  : "long"  = (batch, diag slab s): 64x64 Gram of rows [64s,64s+64)
//                 over full K=4096; also exact fp32 row sums for mu.
//   blk 128..255: "short" = (batch, k-half h): 64x64 off-diag tile rows[0,64)
//                 x rows[64,128) over K-half h.
//   128 threads, 4 warps; warp w owns the whole 64x64 accumulator for k8 step w
//   of each 32-float k-tile (1.0 smem-wavefront/MMA); partials combined via SMEM.
//   3-stage cp.async pipeline; raw-fp32 into tf32 MMA, debiased by CORR.
// Kernel 2 (finish): 256 CTAs = 64 batches x 4 quadrants; off-diag partial is
//   written to BOTH triangles (transposed for the lower one).

#define DINLINE __device__ __forceinline__

static constexpr int Bn = 64;
static constexpr int Cn = 128;
static constexpr int Mn = 4096;
static constexpr int KT = 32;              // k floats per tile
static constexpr int PADB = 144;           // bytes per SMEM row (36 floats)
static constexpr int STAGE_B = 128 * PADB; // 18432
static constexpr int SMEM_B = 3 * STAGE_B; // 55296 (also covers 48KB combine area)

// tf32 truncation debias: 1/(1 - 2 * 2^-11 * (1/(2 ln 2)))
static constexpr float CORR = 1.00070466f;

__device__ float g_part[Bn][4][64 * 64];   // [b][tile: 0=d00,1=d11,2=off-a,3=off-b]
__device__ float g_sums[Bn][Cn];

DINLINE void mma_tf32(float d[4], const uint32_t a[4], uint32_t b0, uint32_t b1) {
    asm volatile(
        "mma.sync.aligned.m16n8k8.row.col.f32.tf32.tf32.f32 "
        "{%0,%1,%2,%3}, {%4,%5,%6,%7}, {%8,%9}, {%0,%1,%2,%3};"
        : "+f"(d[0]), "+f"(d[1]), "+f"(d[2]), "+f"(d[3])
        : "r"(a[0]), "r"(a[1]), "r"(a[2]), "r"(a[3]), "r"(b0), "r"(b1));
}
DINLINE void ldsm_x4(uint32_t r[4], uint32_t addr) {
    asm volatile("ldmatrix.sync.aligned.m8n8.x4.shared.b16 {%0,%1,%2,%3}, [%4];"
                 : "=r"(r[0]), "=r"(r[1]), "=r"(r[2]), "=r"(r[3]) : "r"(addr));
}
DINLINE uint32_t smem_u32(const void* p) {
    uint32_t a;
    asm("{ .reg .u64 t; cvta.to.shared.u64 t, %1; cvt.u32.u64 %0, t; }"
        : "=r"(a) : "l"(p));
    return a;
}
DINLINE void cp16(uint32_t dst, const void* src) {
    asm volatile("cp.async.cg.shared.global [%0], [%1], 16;"
                 :: "r"(dst), "l"(src) : "memory");
}
DINLINE void cp_commit() { asm volatile("cp.async.commit_group;" ::: "memory"); }
template <int N> DINLINE void cp_wait() {
    asm volatile("cp.async.wait_group %0;" :: "n"(N) : "memory");
}

__global__ __launch_bounds__(128, 2)
void covpool_partial(const float* __restrict__ x) {
    extern __shared__ char smem[];
    const uint32_t sb = smem_u32(smem);

    const int t    = threadIdx.x;
    const int warp = t >> 5;
    const int lane = t & 31;
    const int blk  = blockIdx.x;
    const bool diag = blk < 128;

    int b, tileIdx, nkt;
    const float* lsrc;
    uint32_t ldst;
    if (diag) {
        b = blk >> 1;
        const int slab = blk & 1;
        tileIdx = slab;
        nkt = Mn / KT;                       // 128
        const int r = t >> 1, h = t & 1;     // 2 threads per row, 64B each
        lsrc = x + (size_t)b * Cn * Mn + (size_t)(slab * 64 + r) * Mn + h * 16;
        ldst = (uint32_t)(r * PADB + h * 64);
    } else {
        const int b2 = blk - 128;
        b = b2 >> 1;
        const int half = b2 & 1;
        tileIdx = 2 + half;
        nkt = (Mn / 2) / KT;                 // 64
        lsrc = x + (size_t)b * Cn * Mn + (size_t)t * Mn + (size_t)half * (Mn / 2);
        ldst = (uint32_t)(t * PADB);
    }

    // MMA geometry: all warps cover the full 64x64 tile; warp w takes k8 step w.
    const uint32_t kw   = (uint32_t)(warp * 32);   // byte offset within k-tile row
    const uint32_t aoff = (uint32_t)((lane & 15) * PADB + (lane >> 4) * 16) + kw;
    const uint32_t boff = (uint32_t)((diag ? 0 : 64 * PADB)
                          + ((lane & 7) + ((lane >> 4) * 8)) * PADB
                          + ((lane >> 3) & 1) * 16) + kw;
    const int g  = lane >> 2;
    const int tg = lane & 3;

    float acc[4][8][4];
#pragma unroll
    for (int im = 0; im < 4; im++)
#pragma unroll
        for (int in = 0; in < 8; in++)
#pragma unroll
            for (int j = 0; j < 4; j++) acc[im][in][j] = 0.0f;

    float rowsum = 0.0f;

    // prologue: stages 0,1
#pragma unroll
    for (int p = 0; p < 2; p++) {
        const uint32_t d0 = sb + p * STAGE_B + ldst;
        const float* src = lsrc + p * KT;
        if (diag) {
#pragma unroll
            for (int i = 0; i < 4; i++) cp16(d0 + i * 16, src + i * 4);
        } else {
#pragma unroll
            for (int i = 0; i < 8; i++) cp16(d0 + i * 16, src + i * 4);
        }
        cp_commit();
    }

    int cur = 0, iss = 2;
    for (int kt = 0; kt < nkt; kt++) {
        cp_wait<1>();
        __syncthreads();
        if (kt + 2 < nkt) {
            const uint32_t d0 = sb + iss * STAGE_B + ldst;
            const float* src = lsrc + (kt + 2) * KT;
            if (diag) {
#pragma unroll
                for (int i = 0; i < 4; i++) cp16(d0 + i * 16, src + i * 4);
            } else {
#pragma unroll
                for (int i = 0; i < 8; i++) cp16(d0 + i * 16, src + i * 4);
            }
        }
        cp_commit();

        const uint32_t base = sb + cur * STAGE_B;

        if (diag) {  // exact fp32 row sums from this thread's own half row
#pragma unroll
            for (int i = 0; i < 4; i++) {
                float4 v = *(const float4*)(smem + cur * STAGE_B + ldst + i * 16);
                rowsum += v.x + v.y + v.z + v.w;
            }
        }

        uint32_t A[4][4], Bf[4][4];
#pragma unroll
        for (int im = 0; im < 4; im++)
            ldsm_x4(A[im], base + aoff + im * 16 * PADB);
#pragma unroll
        for (int jn = 0; jn < 4; jn++)
            ldsm_x4(Bf[jn], base + boff + jn * 16 * PADB);
#pragma unroll
        for (int im = 0; im < 4; im++)
#pragma unroll
            for (int jn = 0; jn < 4; jn++) {
                mma_tf32(acc[im][2 * jn],     A[im], Bf[jn][0], Bf[jn][1]);
                mma_tf32(acc[im][2 * jn + 1], A[im], Bf[jn][2], Bf[jn][3]);
            }

        cur = (cur == 2) ? 0 : cur + 1;
        iss = (iss == 2) ? 0 : iss + 1;
    }

    // ---- combine 4 warp partials (warps 1-3 -> smem, warp 0 reduces) ----
    __syncthreads();
    float* cs = (float*)smem;
    if (warp > 0) {
        float4* dst = (float4*)(cs + (size_t)(warp - 1) * 4096 + lane * 128);
#pragma unroll
        for (int im = 0; im < 4; im++)
#pragma unroll
            for (int in = 0; in < 8; in++)
                dst[im * 8 + in] = make_float4(acc[im][in][0], acc[im][in][1],
                                               acc[im][in][2], acc[im][in][3]);
    }
    __syncthreads();
    if (warp == 0) {
#pragma unroll
        for (int p = 0; p < 3; p++) {
            const float4* srcp = (const float4*)(cs + (size_t)p * 4096 + lane * 128);
#pragma unroll
            for (int im = 0; im < 4; im++)
#pragma unroll
                for (int in = 0; in < 8; in++) {
                    float4 v = srcp[im * 8 + in];
                    acc[im][in][0] += v.x; acc[im][in][1] += v.y;
                    acc[im][in][2] += v.z; acc[im][in][3] += v.w;
                }
        }
        float* gp = g_part[b][tileIdx];
#pragma unroll
        for (int im = 0; im < 4; im++) {
            const int r0 = im * 16 + g;
#pragma unroll
            for (int in = 0; in < 8; in++) {
                const int c0 = in * 8 + 2 * tg;
                *(float2*)(gp + r0 * 64 + c0) =
                    make_float2(acc[im][in][0], acc[im][in][1]);
                *(float2*)(gp + (r0 + 8) * 64 + c0) =
                    make_float2(acc[im][in][2], acc[im][in][3]);
            }
        }
    }
    if (diag) {
        rowsum += __shfl_xor_sync(0xffffffffu, rowsum, 1);
        if ((t & 1) == 0) g_sums[b][(tileIdx & 1) * 64 + (t >> 1)] = rowsum;
    }
}

__global__ __launch_bounds__(256, 2)
void covpool_finish(float* __restrict__ y) {
    __shared__ float mu[Cn];
    const int t = threadIdx.x;
    const int b = blockIdx.x >> 2;
    const int q = blockIdx.x & 3;
    if (t < Cn) mu[t] = g_sums[b][t] * (1.0f / (float)Mn);
    __syncthreads();

    const float a = CORR * (1.0f / (float)Mn);
    float* yb = y + (size_t)b * Cn * Cn;

    if (q == 0 || q == 3) {                 // diagonal quadrants
        const int d = (q == 0) ? 0 : 64;
        const float4* G = (const float4*)g_part[b][(q == 0) ? 0 : 1];
#pragma unroll
        for (int k = 0; k < 4; k++) {
            const int e4 = t + k * 256;     // float4 idx in [0,1024)
            const int i  = e4 >> 4;
            const int j4 = e4 & 15;
            const float4 gv = G[e4];
            const float mr = mu[d + i];
            const float4 m = ((const float4*)mu)[(d >> 2) + j4];
            float4 o;
            o.x = gv.x * a - mr * m.x;  o.y = gv.y * a - mr * m.y;
            o.z = gv.z * a - mr * m.z;  o.w = gv.w * a - mr * m.w;
            ((float4*)(yb + (size_t)(d + i) * Cn + d))[j4] = o;
        }
    } else if (q == 1) {                    // upper-right: rows 0-63, cols 64-127
        const float4* Ga = (const float4*)g_part[b][2];
        const float4* Gb = (const float4*)g_part[b][3];
#pragma unroll
        for (int k = 0; k < 4; k++) {
            const int e4 = t + k * 256;
            const int i  = e4 >> 4;
            const int j4 = e4 & 15;
            float4 ga = Ga[e4], gb = Gb[e4];
            const float mr = mu[i];
            const float4 m = ((const float4*)mu)[16 + j4];
            float4 o;
            o.x = (ga.x + gb.x) * a - mr * m.x;
            o.y = (ga.y + gb.y) * a - mr * m.y;
            o.z = (ga.z + gb.z) * a - mr * m.z;
            o.w = (ga.w + gb.w) * a - mr * m.w;
            ((float4*)(yb + (size_t)i * Cn + 64))[j4] = o;
        }
    } else {                                // lower-left: transpose of q1 source
        const float* Ga = g_part[b][2];
        const float* Gb = g_part[b][3];
#pragma unroll
        for (int k = 0; k < 4; k++) {
            const int e4 = t + k * 256;
            const int jj = e4 >> 4;          // 0..63 -> out row 64+jj
            const int i0 = (e4 & 15) * 4;    // out cols i0..i0+3
            const float mr = mu[64 + jj];
            float4 o;
            o.x = (Ga[(i0 + 0) * 64 + jj] + Gb[(i0 + 0) * 64 + jj]) * a - mr * mu[i0 + 0];
            o.y = (Ga[(i0 + 1) * 64 + jj] + Gb[(i0 + 1) * 64 + jj]) * a - mr * mu[i0 + 1];
            o.z = (Ga[(i0 + 2) * 64 + jj] + Gb[(i0 + 2) * 64 + jj]) * a - mr * mu[i0 + 2];
            o.w = (Ga[(i0 + 3) * 64 + jj] + Gb[(i0 + 3) * 64 + jj]) * a - mr * mu[i0 + 3];
            *(float4*)(yb + (size_t)(64 + jj) * Cn + i0) = o;
        }
    }
}

extern "C" void kernel_launch(void* const* d_in, const int* in_sizes, int n_in,
                              void* d_out, int out_size) {
    (void)in_sizes; (void)n_in; (void)out_size;
    const float* x = (const float*)d_in[0];
    float* y = (float*)d_out;
    cudaFuncSetAttribute(covpool_partial,
                         cudaFuncAttributeMaxDynamicSharedMemorySize, SMEM_B);
    covpool_partial<<<4 * Bn, 128, SMEM_B>>>(x);
    covpool_finish<<<4 * Bn, 256>>>(y);
}